// round 1
// baseline (speedup 1.0000x reference)
#include <cuda_runtime.h>
#include <cuda_bf16.h>
#include <cstdint>

#define DIM 4096
#define THREADS 256
#define REGS 16   // elements per thread

// XOR swizzle making all three smem access patterns bank-conflict-free.
// phys = a ^ ((a>>5)&0xF) ^ (((a>>8)&1)<<4); bijective on [0,4096).
__device__ __forceinline__ int swz(int a) {
    return a ^ ((a >> 5) & 0x0F) ^ (((a >> 8) & 1) << 4);
}

// In-register 16-point Walsh-Hadamard (unnormalized butterflies).
__device__ __forceinline__ void fwht16(float r[REGS]) {
#pragma unroll
    for (int h = 1; h < 16; h <<= 1) {
#pragma unroll
        for (int k = 0; k < 16; k++) {
            if ((k & h) == 0) {
                float a = r[k];
                float b = r[k + h];
                r[k]     = a + b;
                r[k + h] = a - b;
            }
        }
    }
}

__global__ __launch_bounds__(THREADS, 8)
void fwht4096_kernel(const float* __restrict__ x, float* __restrict__ y) {
    __shared__ float s[DIM];

    const int row = blockIdx.x;
    const float* xr = x + (size_t)row * DIM;
    float*       yr = y + (size_t)row * DIM;
    const int t = threadIdx.x;

    float r[REGS];

    // ---- Phase 1: thread t holds i = (j<<8) | t  (j = 0..15)  -> FWHT bits 8..11
    // Coalesced loads: for fixed j, warp reads 128B-contiguous.
#pragma unroll
    for (int j = 0; j < REGS; j++) {
        r[j] = xr[(j << 8) | t];
    }
    fwht16(r);

    // ---- Exchange 1: write pattern A, read pattern B
#pragma unroll
    for (int j = 0; j < REGS; j++) {
        s[swz((j << 8) | t)] = r[j];
    }
    __syncthreads();

    const int u_hi = t >> 4;    // supplies bits 8..11 of i
    const int u_lo = t & 15;    // supplies bits 0..3 of i
#pragma unroll
    for (int j = 0; j < REGS; j++) {
        r[j] = s[swz((u_hi << 8) | (j << 4) | u_lo)];
    }

    // ---- Phase 2: FWHT over bits 4..7
    fwht16(r);

    // ---- Exchange 2: write pattern B (same addresses this thread just read ->
    // no intra-exchange hazard), sync, read pattern C.
    __syncthreads();   // ensure every thread finished reading pattern B before overwrite
#pragma unroll
    for (int j = 0; j < REGS; j++) {
        s[swz((u_hi << 8) | (j << 4) | u_lo)] = r[j];
    }
    __syncthreads();

#pragma unroll
    for (int j = 0; j < REGS; j++) {
        r[j] = s[swz((t << 4) | j)];
    }

    // ---- Phase 3: FWHT over bits 0..3
    fwht16(r);

    // ---- Scale by 1/sqrt(4096) = 1/64 (exact) and store.
    // Thread t holds 16 contiguous elements [t*16, t*16+16) -> 4x STG.128,
    // warp covers 2KB contiguous.
    const float sc = 0.015625f;
#pragma unroll
    for (int j = 0; j < REGS; j++) r[j] *= sc;

    float4* y4 = reinterpret_cast<float4*>(yr);
#pragma unroll
    for (int q = 0; q < 4; q++) {
        float4 v;
        v.x = r[q * 4 + 0];
        v.y = r[q * 4 + 1];
        v.z = r[q * 4 + 2];
        v.w = r[q * 4 + 3];
        y4[t * 4 + q] = v;
    }
}

extern "C" void kernel_launch(void* const* d_in, const int* in_sizes, int n_in,
                              void* d_out, int out_size) {
    const float* x = (const float*)d_in[0];
    float* y = (float*)d_out;
    const int n = in_sizes[0];
    const int rows = n / DIM;   // 8192
    fwht4096_kernel<<<rows, THREADS>>>(x, y);
}

// round 3
// speedup vs baseline: 1.0248x; 1.0248x over previous
#include <cuda_runtime.h>
#include <cuda_bf16.h>
#include <cstdint>

#define DIM 4096
#define THREADS 64
#define REGS 64          // elements per thread
#define ROW_STRIDE 68    // 64 + 4 words padding -> conflict-free LDS.128

// In-register 64-point Walsh-Hadamard (unnormalized butterflies).
__device__ __forceinline__ void fwht64(float r[REGS]) {
#pragma unroll
    for (int h = 1; h < REGS; h <<= 1) {
#pragma unroll
        for (int k = 0; k < REGS; k++) {
            if ((k & h) == 0) {
                float a = r[k];
                float b = r[k + h];
                r[k]     = a + b;
                r[k + h] = a - b;
            }
        }
    }
}

__global__ __launch_bounds__(THREADS)
void fwht4096_kernel(const float* __restrict__ x, float* __restrict__ y) {
    __shared__ float s[REGS * ROW_STRIDE];   // 17408 B

    const int row = blockIdx.x;
    const int t   = threadIdx.x;

    const float4* x4 = reinterpret_cast<const float4*>(x + (size_t)row * DIM);
    float*        yr = y + (size_t)row * DIM;

    float r[REGS];

    // ---- Load: thread t owns logical elements [t*64, t*64+64) -> 16x LDG.128,
    // warp covers 8KB contiguous.
#pragma unroll
    for (int m = 0; m < 16; m++) {
        float4 v = x4[t * 16 + m];
        r[4 * m + 0] = v.x;
        r[4 * m + 1] = v.y;
        r[4 * m + 2] = v.z;
        r[4 * m + 3] = v.w;
    }

    // ---- Phase 1: FWHT over low 6 bits (the j index within this thread).
    fwht64(r);

    // ---- Exchange: value of logical (hi=t, lo=j) -> s[j*68 + t].
    // Per unrolled j: lane t gives bank (68j + t) % 32 == distinct -> conflict-free.
#pragma unroll
    for (int j = 0; j < REGS; j++) {
        s[j * ROW_STRIDE + t] = r[j];
    }
    __syncthreads();

    // ---- Read row t: thread t now owns logical (hi=k, lo=t) for k=0..63.
    // 16x LDS.128; row byte-offset t*272 is 16B-aligned; quarter-warp bank
    // groups 4*((t&7)+m) mod 32 are disjoint -> conflict-free.
    const float4* s4 = reinterpret_cast<const float4*>(&s[t * ROW_STRIDE]);
#pragma unroll
    for (int m = 0; m < 16; m++) {
        float4 v = s4[m];
        r[4 * m + 0] = v.x;
        r[4 * m + 1] = v.y;
        r[4 * m + 2] = v.z;
        r[4 * m + 3] = v.w;
    }

    // ---- Phase 2: FWHT over high 6 bits.
    fwht64(r);

    // ---- Scale by 1/sqrt(4096) = 1/64 (exact) and store.
    // y[k*64 + t]: fixed k, lanes t -> 128B contiguous per warp, coalesced.
    const float sc = 0.015625f;
#pragma unroll
    for (int k = 0; k < REGS; k++) {
        yr[k * 64 + t] = r[k] * sc;
    }
}

extern "C" void kernel_launch(void* const* d_in, const int* in_sizes, int n_in,
                              void* d_out, int out_size) {
    const float* x = (const float*)d_in[0];
    float* y = (float*)d_out;
    const int n = in_sizes[0];
    const int rows = n / DIM;   // 8192
    fwht4096_kernel<<<rows, THREADS>>>(x, y);
}

// round 4
// speedup vs baseline: 1.4147x; 1.3804x over previous
#include <cuda_runtime.h>
#include <cuda_bf16.h>
#include <cstdint>

#define DIM 4096
#define THREADS 128
#define SROW 36   // padded stride (words) per 32-word group: conflict-free both patterns

// In-register 32-point Walsh-Hadamard (unnormalized butterflies).
__device__ __forceinline__ void fwht32(float r[32]) {
#pragma unroll
    for (int h = 1; h < 32; h <<= 1) {
#pragma unroll
        for (int k = 0; k < 32; k++) {
            if ((k & h) == 0) {
                float a = r[k];
                float b = r[k + h];
                r[k]     = a + b;
                r[k + h] = a - b;
            }
        }
    }
}

__global__ __launch_bounds__(THREADS, 10)
void fwht4096_kernel(const float* __restrict__ x, float* __restrict__ y) {
    // Logical element i (12 bits) stored at phys(i) = (i>>5)*SROW + (i&31).
    __shared__ float s[128 * SROW];   // 18432 B

    const int t    = threadIdx.x;
    const int w    = t >> 5;
    const int lane = t & 31;

    const float* xr = x + (size_t)blockIdx.x * DIM;
    float*       yr = y + (size_t)blockIdx.x * DIM;

    float r[32];

    // ---- Load: r[k] = x[k*128 + t]. Per warp per k: one contiguous 128B line.
#pragma unroll
    for (int k = 0; k < 32; k++)
        r[k] = xr[k * 128 + t];

    // ---- Phase A: butterflies over i bits 7..11 (== bits of k).
    fwht32(r);

    // ---- Exchange 1 write: i = k*128 + t  ->  phys = (4k + w)*36 + lane.
    // Banks (16k + 4w + lane) mod 32: distinct per lane -> conflict-free.
#pragma unroll
    for (int k = 0; k < 32; k++)
        s[(4 * k + w) * SROW + lane] = r[k];
    __syncthreads();

    // ---- Exchange 1 read: thread t owns i = c + (t&3)*32 + (t>>2)*128, c=0..31.
    // i>>5 == t, so phys = t*36 + c : contiguous, 144B-aligned -> 8x LDS.128.
    // Banks 4(t+m) mod 32: disjoint per quarter-warp -> conflict-free.
    {
        const float4* s4 = reinterpret_cast<const float4*>(&s[t * SROW]);
#pragma unroll
        for (int m = 0; m < 8; m++) {
            float4 v = s4[m];
            r[4*m+0] = v.x; r[4*m+1] = v.y; r[4*m+2] = v.z; r[4*m+3] = v.w;
        }
    }

    // ---- Phase B part 1: butterflies over i bits 0..4 (== bits of c).
    fwht32(r);

    // ---- Phase B part 2: bits 5,6 of i live in lane bits 0,1 -> shuffle stages.
    {
        const float sgn5 = (t & 1) ? -1.0f : 1.0f;
#pragma unroll
        for (int k = 0; k < 32; k++) {
            float o = __shfl_xor_sync(0xFFFFFFFFu, r[k], 1);
            r[k] = fmaf(sgn5, r[k], o);   // low: a+b, high: a-b
        }
        const float sgn6 = (t & 2) ? -1.0f : 1.0f;
#pragma unroll
        for (int k = 0; k < 32; k++) {
            float o = __shfl_xor_sync(0xFFFFFFFFu, r[k], 2);
            r[k] = fmaf(sgn6, r[k], o);
        }
    }

    // ---- Exchange 2 write: same phys range this thread just read
    // ([36t, 36t+32)) -> no barrier needed before the write. 8x STS.128.
    {
        float4* s4 = reinterpret_cast<float4*>(&s[t * SROW]);
#pragma unroll
        for (int m = 0; m < 8; m++) {
            float4 v;
            v.x = r[4*m+0]; v.y = r[4*m+1]; v.z = r[4*m+2]; v.w = r[4*m+3];
            s4[m] = v;
        }
    }
    __syncthreads();

    // ---- Exchange 2 read + scaled store: i = k*128 + t, coalesced STG.32.
    const float sc = 0.015625f;   // 1/sqrt(4096), exact
#pragma unroll
    for (int k = 0; k < 32; k++)
        yr[k * 128 + t] = s[(4 * k + w) * SROW + lane] * sc;
}

extern "C" void kernel_launch(void* const* d_in, const int* in_sizes, int n_in,
                              void* d_out, int out_size) {
    const float* x = (const float*)d_in[0];
    float* y = (float*)d_out;
    const int n = in_sizes[0];
    const int rows = n / DIM;   // 8192
    fwht4096_kernel<<<rows, THREADS>>>(x, y);
}